// round 14
// baseline (speedup 1.0000x reference)
#include <cuda_runtime.h>
#include <cuda_fp16.h>
#include <math.h>
#include <stdint.h>

#define NODES 50000
#define NODES_PAD 50048            // 391 tiles * 128
#define EDGES 800000
#define NTILES 391

// ---------------- scratch (static device globals; no allocs allowed) ----------
// Pure fp16 pipeline: activations and weights quantized to fp16, fp32 accum.
__device__ __align__(128) unsigned char g_a1[(size_t)NODES_PAD * 1024]; // [N][512 f16]: [0,512)B agg, [512,1024)B x
__device__ __align__(128) unsigned char g_b1[256 * 1024];               // [256 n][512 f16]: W1l;W1r transposed
__device__ __align__(128) unsigned char g_b2[256 * 512];                // [256 n][256 f16]: W2l|W2r transposed
__device__ __align__(128) unsigned char g_pl[(size_t)NODES_PAD * 256];  // [N][128 f16]: h@W2l (gathered later)
__device__ __align__(128) float g_pr[(size_t)NODES_PAD * 128];          // [N][128 f32]: h@W2r (self term)
__device__ int   g_cnt [NODES];
__device__ float g_inv [NODES];
__device__ int   g_src [EDGES];
__device__ int   g_dst [EDGES];
__device__ int   g_rank[EDGES];         // rank of edge within its dst bucket
__device__ int   g_off [NODES];
__device__ int   g_esrc[EDGES];
__device__ int   g_total;

// ---------------- PTX helpers ---------------------------------------------------
__device__ __forceinline__ uint32_t smem_u32(const void* p) {
    uint32_t a;
    asm("{ .reg .u64 t; cvta.to.shared.u64 t, %1; cvt.u32.u64 %0, t; }" : "=r"(a) : "l"(p));
    return a;
}
#define SW128(o) ((o) ^ (((o) >> 3) & 0x70))

__device__ __forceinline__ void cp16(uint32_t dst, const void* src) {
    asm volatile("cp.async.cg.shared.global [%0], [%1], 16;" :: "r"(dst), "l"(src));
}
#define CP_COMMIT() asm volatile("cp.async.commit_group;" ::: "memory")
#define CP_WAIT(n)  asm volatile("cp.async.wait_group %0;" :: "n"(n) : "memory")

__device__ __forceinline__ void ldsm4(uint32_t addr, uint32_t* r) {
    asm volatile("ldmatrix.sync.aligned.m8n8.x4.shared.b16 {%0,%1,%2,%3}, [%4];"
        : "=r"(r[0]), "=r"(r[1]), "=r"(r[2]), "=r"(r[3]) : "r"(addr));
}
__device__ __forceinline__ void mma16816(float* c, const uint32_t* a, uint32_t b0, uint32_t b1) {
    asm volatile("mma.sync.aligned.m16n8k16.row.col.f32.f16.f16.f32 "
        "{%0,%1,%2,%3}, {%4,%5,%6,%7}, {%8,%9}, {%0,%1,%2,%3};"
        : "+f"(c[0]), "+f"(c[1]), "+f"(c[2]), "+f"(c[3])
        : "r"(a[0]), "r"(a[1]), "r"(a[2]), "r"(a[3]), "r"(b0), "r"(b1));
}

__device__ __forceinline__ unsigned short f2h(float v) {
    __half h = __float2half_rn(v);
    return *reinterpret_cast<unsigned short*>(&h);
}
__device__ __forceinline__ uint32_t pack2h(float a, float b) {
    return (uint32_t)f2h(a) | ((uint32_t)f2h(b) << 16);
}
__device__ __forceinline__ float2 uph(uint32_t w) {
    return __half22float2(*reinterpret_cast<__half2*>(&w));
}

// ------- fused prep: zero counters, weights -> fp16 streams, x -> fp16 copy -----
#define WPREP_N (256 * 512 + 256 * 256)     // 196608
__global__ void k_prep(const float* __restrict__ W1l, const float* __restrict__ W1r,
                       const float* __restrict__ W2l, const float* __restrict__ W2r,
                       const float* __restrict__ x) {
    int id = blockIdx.x * blockDim.x + threadIdx.x;
    if (id < NODES) g_cnt[id] = 0;
    if (id == 0) g_total = 0;
    if (id < 256 * 512) {
        int n = id >> 9, k = id & 511;
        float w = (k < 256) ? W1l[k * 256 + n] : W1r[(k - 256) * 256 + n];
        *(unsigned short*)(g_b1 + (size_t)n * 1024 + 2 * k) = f2h(w);
    } else if (id < WPREP_N) {
        int id2 = id - 256 * 512;
        int n = id2 >> 8, k = id2 & 255;
        float w = (n < 128) ? W2l[k * 128 + n] : W2r[k * 128 + (n - 128)];
        *(unsigned short*)(g_b2 + (size_t)n * 512 + 2 * k) = f2h(w);
    } else if (id < WPREP_N + NODES * 32) {
        int id2 = id - WPREP_N;
        int node = id2 >> 5;
        int col  = (id2 & 31) * 8;
        const float4* src = (const float4*)(x + (size_t)node * 256 + col);
        float4 a = src[0], b = src[1];
        uint4 o;
        o.x = pack2h(a.x, a.y);
        o.y = pack2h(a.z, a.w);
        o.z = pack2h(b.x, b.y);
        o.w = pack2h(b.z, b.w);
        *(uint4*)(g_a1 + (size_t)node * 1024 + 512 + col * 2) = o;
    }
}

// ------- edge decode + degree count; atomic result IS the bucket rank ----------
__global__ void k_edges(const void* __restrict__ ei_raw) {
    int e = blockIdx.x * blockDim.x + threadIdx.x;
    if (e >= EDGES) return;
    const int* w = (const int*)ei_raw;
    bool is64 = ((w[1] | w[3] | w[5] | w[7] | w[9] | w[11] | w[13] | w[15]) == 0);
    int s, d;
    if (is64) {
        const long long* e64 = (const long long*)ei_raw;
        s = (int)e64[e];
        d = (int)e64[EDGES + e];
    } else {
        s = w[e];
        d = w[EDGES + e];
    }
    g_src[e] = s;
    g_dst[e] = d;
    g_rank[e] = atomicAdd(&g_cnt[d], 1);
}

// ------- bucket allocation: per-block scan + one global atomic; also 1/deg -----
__global__ void k_alloc() {
    __shared__ int s[256];
    __shared__ int base;
    int t = threadIdx.x;
    int i = blockIdx.x * 256 + t;
    int v = (i < NODES) ? g_cnt[i] : 0;
    s[t] = v;
    __syncthreads();
#pragma unroll
    for (int d = 1; d < 256; d <<= 1) {
        int add = (t >= d) ? s[t - d] : 0;
        __syncthreads();
        s[t] += add;
        __syncthreads();
    }
    int incl = s[t];
    if (t == 255) base = atomicAdd(&g_total, incl);
    __syncthreads();
    if (i < NODES) {
        g_off[i] = base + incl - v;
        g_inv[i] = 1.f / fmaxf((float)v, 1.f);
    }
}

// ------- bucket fill: atomic-free scatter via precomputed rank ------------------
__global__ void k_fill() {
    int e = blockIdx.x * blockDim.x + threadIdx.x;
    if (e >= EDGES) return;
    g_esrc[g_off[g_dst[e]] + g_rank[e]] = g_src[e];
}

// ------------- layer-1 gather (fp16 rows, fp32 accumulate) -----------------------
// One warp per node; lane owns 8 cols (16B fp16); 4-edge unroll.
__global__ void k_gather1() {
    int node = (blockIdx.x * blockDim.x + threadIdx.x) >> 5;
    if (node >= NODES) return;
    int lane = threadIdx.x & 31;
    int boff = lane * 16;

    int e   = g_off[node];
    int end = e + g_cnt[node];
    float acc[8];
#pragma unroll
    for (int i = 0; i < 8; i++) acc[i] = 0.f;

    for (; e + 3 < end; e += 4) {
        int s0 = g_esrc[e], s1 = g_esrc[e + 1], s2 = g_esrc[e + 2], s3 = g_esrc[e + 3];
        uint4 v0 = *(const uint4*)(g_a1 + (size_t)s0 * 1024 + 512 + boff);
        uint4 v1 = *(const uint4*)(g_a1 + (size_t)s1 * 1024 + 512 + boff);
        uint4 v2 = *(const uint4*)(g_a1 + (size_t)s2 * 1024 + 512 + boff);
        uint4 v3 = *(const uint4*)(g_a1 + (size_t)s3 * 1024 + 512 + boff);
        float2 f;
        f = uph(v0.x); acc[0] += f.x; acc[1] += f.y;
        f = uph(v0.y); acc[2] += f.x; acc[3] += f.y;
        f = uph(v0.z); acc[4] += f.x; acc[5] += f.y;
        f = uph(v0.w); acc[6] += f.x; acc[7] += f.y;
        f = uph(v1.x); acc[0] += f.x; acc[1] += f.y;
        f = uph(v1.y); acc[2] += f.x; acc[3] += f.y;
        f = uph(v1.z); acc[4] += f.x; acc[5] += f.y;
        f = uph(v1.w); acc[6] += f.x; acc[7] += f.y;
        f = uph(v2.x); acc[0] += f.x; acc[1] += f.y;
        f = uph(v2.y); acc[2] += f.x; acc[3] += f.y;
        f = uph(v2.z); acc[4] += f.x; acc[5] += f.y;
        f = uph(v2.w); acc[6] += f.x; acc[7] += f.y;
        f = uph(v3.x); acc[0] += f.x; acc[1] += f.y;
        f = uph(v3.y); acc[2] += f.x; acc[3] += f.y;
        f = uph(v3.z); acc[4] += f.x; acc[5] += f.y;
        f = uph(v3.w); acc[6] += f.x; acc[7] += f.y;
    }
    for (; e < end; e++) {
        int s0 = g_esrc[e];
        uint4 v0 = *(const uint4*)(g_a1 + (size_t)s0 * 1024 + 512 + boff);
        float2 f;
        f = uph(v0.x); acc[0] += f.x; acc[1] += f.y;
        f = uph(v0.y); acc[2] += f.x; acc[3] += f.y;
        f = uph(v0.z); acc[4] += f.x; acc[5] += f.y;
        f = uph(v0.w); acc[6] += f.x; acc[7] += f.y;
    }
    float inv = g_inv[node];
    uint4 o;
    o.x = pack2h(acc[0] * inv, acc[1] * inv);
    o.y = pack2h(acc[2] * inv, acc[3] * inv);
    o.z = pack2h(acc[4] * inv, acc[5] * inv);
    o.w = pack2h(acc[6] * inv, acc[7] * inv);
    *(uint4*)(g_a1 + (size_t)node * 1024 + boff) = o;
}

// ------- fused GEMM: per-CTA row block computes h (smem) then p ------------------
// Phase 1: h[128,256] = relu(A1[128,512]@B1 + b1), kept in smem SW128 chunk tiles.
// Phase 2: p[128,256] = h@B2 with A from smem h; left->g_pl fp16, right->g_pr f32.
#define STAGE_BYTES 32768                  // phase-1 stage: A 16KB + B 16KB
#define H_BASE (3 * STAGE_BYTES)           // 98304: h tiles (4 x 16KB = 64KB)
#define SMEM_DYN (H_BASE + 65536)          // 163840

__global__ __launch_bounds__(256, 1) void k_gemm_fused(const float* __restrict__ bias1) {
    extern __shared__ __align__(128) unsigned char dsm[];
    const int t      = threadIdx.x;
    const int lane   = t & 31;
    const int wid    = t >> 5;
    const int warp_m = wid & 3;
    const int warp_n = wid >> 2;
    const int row0   = blockIdx.x * 128;
    const uint32_t base  = smem_u32(dsm);
    const uint32_t hbase = base + H_BASE;

    const int lrow = t >> 1;
    const int ch0  = (t & 1) * 4;
    const int lj = lane >> 3;
    const int lr = lane & 7;
    const int qr = lane >> 2;
    const int qc = (lane & 3) * 2;

    float c[2][8][4];

    // ---------------- phase 1: two column halves of h -------------------------
#pragma unroll 1
    for (int ch = 0; ch < 2; ch++) {
        const int col0 = ch * 128;
#pragma unroll
        for (int i = 0; i < 2; i++)
#pragma unroll
            for (int j = 0; j < 8; j++)
#pragma unroll
                for (int q = 0; q < 4; q++) c[i][j][q] = 0.f;

        auto load_tile1 = [&](int kt, int s) {
            uint32_t sa = base + s * STAGE_BYTES;
            uint32_t sb = sa + 16384;
            const unsigned char* srcA = g_a1 + (size_t)(row0 + lrow) * 1024 + (size_t)kt * 128 + ch0 * 16;
#pragma unroll
            for (int i = 0; i < 4; i++)
                cp16(sa + SW128(lrow * 128 + (ch0 + i) * 16), srcA + i * 16);
            const unsigned char* srcB = g_b1 + (size_t)(col0 + lrow) * 1024 + (size_t)kt * 128 + ch0 * 16;
#pragma unroll
            for (int i = 0; i < 4; i++)
                cp16(sb + SW128(lrow * 128 + (ch0 + i) * 16), srcB + i * 16);
            CP_COMMIT();
        };
        auto compute1 = [&](int s) {
            uint32_t sa = base + s * STAGE_BYTES;
            uint32_t sb = sa + 16384;
#pragma unroll
            for (int ks = 0; ks < 4; ks++) {
                int cb = ks * 32 + (lj >> 1) * 16;
                uint32_t af[2][4];
#pragma unroll
                for (int mm = 0; mm < 2; mm++) {
                    int row = warp_m * 32 + mm * 16 + (lj & 1) * 8 + lr;
                    ldsm4(sa + SW128(row * 128 + cb), af[mm]);
                }
                uint32_t bf[4][4];
#pragma unroll
                for (int np = 0; np < 4; np++) {
                    int row = warp_n * 64 + np * 16 + (lj & 1) * 8 + lr;
                    ldsm4(sb + SW128(row * 128 + cb), bf[np]);
                }
#pragma unroll
                for (int mm = 0; mm < 2; mm++)
#pragma unroll
                    for (int nn = 0; nn < 8; nn++)
                        mma16816(c[mm][nn], af[mm], bf[nn >> 1][nn & 1], bf[nn >> 1][(nn & 1) + 2]);
            }
        };

        load_tile1(0, 0);
        load_tile1(1, 1);
#pragma unroll 1
        for (int kt = 0; kt < 8; kt++) {
            if (kt == 7) { CP_WAIT(0); } else { CP_WAIT(1); }
            __syncthreads();
            if (kt + 2 < 8) load_tile1(kt + 2, (kt + 2) % 3);
            compute1(kt % 3);
        }

        // epilogue: relu(h+b1) -> smem h chunk tiles (SW128)
#pragma unroll
        for (int mm = 0; mm < 2; mm++) {
#pragma unroll
            for (int nn = 0; nn < 8; nn++) {
                int col = col0 + warp_n * 64 + nn * 8 + qc;
                int chunk = col >> 6;
                int coff  = (col & 63) * 2;
#pragma unroll
                for (int h = 0; h < 2; h++) {
                    int hrow = warp_m * 32 + mm * 16 + qr + h * 8;
                    float v0 = fmaxf(c[mm][nn][2 * h + 0] + __ldg(&bias1[col]), 0.f);
                    float v1 = fmaxf(c[mm][nn][2 * h + 1] + __ldg(&bias1[col + 1]), 0.f);
                    uint32_t addr = hbase + chunk * 16384 + SW128(hrow * 128 + coff);
                    asm volatile("st.shared.b32 [%0], %1;" :: "r"(addr), "r"(pack2h(v0, v1)) : "memory");
                }
            }
        }
        __syncthreads();
    }

    // ---------------- phase 2: p = h @ B2 (A from smem h) ----------------------
#pragma unroll 1
    for (int ch = 0; ch < 2; ch++) {
        const int col0 = ch * 128;
#pragma unroll
        for (int i = 0; i < 2; i++)
#pragma unroll
            for (int j = 0; j < 8; j++)
#pragma unroll
                for (int q = 0; q < 4; q++) c[i][j][q] = 0.f;

        auto load_tile2 = [&](int kt, int s) {
            uint32_t sb = base + s * 16384;
            const unsigned char* srcB = g_b2 + (size_t)(col0 + lrow) * 512 + (size_t)kt * 128 + ch0 * 16;
#pragma unroll
            for (int i = 0; i < 4; i++)
                cp16(sb + SW128(lrow * 128 + (ch0 + i) * 16), srcB + i * 16);
            CP_COMMIT();
        };
        auto compute2 = [&](int kt, int s) {
            uint32_t sa = hbase + kt * 16384;
            uint32_t sb = base + s * 16384;
#pragma unroll
            for (int ks = 0; ks < 4; ks++) {
                int cb = ks * 32 + (lj >> 1) * 16;
                uint32_t af[2][4];
#pragma unroll
                for (int mm = 0; mm < 2; mm++) {
                    int row = warp_m * 32 + mm * 16 + (lj & 1) * 8 + lr;
                    ldsm4(sa + SW128(row * 128 + cb), af[mm]);
                }
                uint32_t bf[4][4];
#pragma unroll
                for (int np = 0; np < 4; np++) {
                    int row = warp_n * 64 + np * 16 + (lj & 1) * 8 + lr;
                    ldsm4(sb + SW128(row * 128 + cb), bf[np]);
                }
#pragma unroll
                for (int mm = 0; mm < 2; mm++)
#pragma unroll
                    for (int nn = 0; nn < 8; nn++)
                        mma16816(c[mm][nn], af[mm], bf[nn >> 1][nn & 1], bf[nn >> 1][(nn & 1) + 2]);
            }
        };

        load_tile2(0, 0);
        load_tile2(1, 1);
#pragma unroll 1
        for (int kt = 0; kt < 4; kt++) {
            if (kt == 3) { CP_WAIT(0); } else { CP_WAIT(1); }
            __syncthreads();
            if (kt + 2 < 4) load_tile2(kt + 2, (kt + 2) % 3);
            compute2(kt, kt % 3);
        }

        // epilogue: ch==0 -> g_pl fp16, ch==1 -> g_pr f32
#pragma unroll
        for (int mm = 0; mm < 2; mm++) {
#pragma unroll
            for (int nn = 0; nn < 8; nn++) {
                int col = col0 + warp_n * 64 + nn * 8 + qc;
#pragma unroll
                for (int h = 0; h < 2; h++) {
                    int row = row0 + warp_m * 32 + mm * 16 + qr + h * 8;
                    float v0 = c[mm][nn][2 * h + 0];
                    float v1 = c[mm][nn][2 * h + 1];
                    if (ch == 0) {
                        *(uint32_t*)(g_pl + (size_t)row * 256 + 2 * col) = pack2h(v0, v1);
                    } else {
                        *(float2*)(g_pr + (size_t)row * 128 + (col - 128)) = make_float2(v0, v1);
                    }
                }
            }
        }
        __syncthreads();
    }
}

// ---- layer-2 gather fused with epilogue: out = sigmoid(mean(p_l)+b2+p_r) -------
// One warp per node; lane owns 4 cols (8B fp16 per edge); 4-edge unroll.
__global__ void k_gather2_final(const float* __restrict__ b2,
                                float* __restrict__ out) {
    int node = (blockIdx.x * blockDim.x + threadIdx.x) >> 5;
    if (node >= NODES) return;
    int lane = threadIdx.x & 31;
    int c = lane * 4;

    int e   = g_off[node];
    int end = e + g_cnt[node];
    float4 acc = make_float4(0.f, 0.f, 0.f, 0.f);
    for (; e + 3 < end; e += 4) {
        int s0 = g_esrc[e], s1 = g_esrc[e + 1], s2 = g_esrc[e + 2], s3 = g_esrc[e + 3];
        uint2 v0 = *(const uint2*)(g_pl + (size_t)s0 * 256 + 2 * c);
        uint2 v1 = *(const uint2*)(g_pl + (size_t)s1 * 256 + 2 * c);
        uint2 v2 = *(const uint2*)(g_pl + (size_t)s2 * 256 + 2 * c);
        uint2 v3 = *(const uint2*)(g_pl + (size_t)s3 * 256 + 2 * c);
        float2 f;
        f = uph(v0.x); acc.x += f.x; acc.y += f.y;
        f = uph(v0.y); acc.z += f.x; acc.w += f.y;
        f = uph(v1.x); acc.x += f.x; acc.y += f.y;
        f = uph(v1.y); acc.z += f.x; acc.w += f.y;
        f = uph(v2.x); acc.x += f.x; acc.y += f.y;
        f = uph(v2.y); acc.z += f.x; acc.w += f.y;
        f = uph(v3.x); acc.x += f.x; acc.y += f.y;
        f = uph(v3.y); acc.z += f.x; acc.w += f.y;
    }
    for (; e < end; e++) {
        int s0 = g_esrc[e];
        uint2 v0 = *(const uint2*)(g_pl + (size_t)s0 * 256 + 2 * c);
        float2 f;
        f = uph(v0.x); acc.x += f.x; acc.y += f.y;
        f = uph(v0.y); acc.z += f.x; acc.w += f.y;
    }
    float inv = g_inv[node];
    float4 bb = *(const float4*)(b2 + c);
    float4 rr = *(const float4*)(g_pr + (size_t)node * 128 + c);
    float4 o;
    o.x = 1.f / (1.f + expf(-(acc.x * inv + bb.x + rr.x)));
    o.y = 1.f / (1.f + expf(-(acc.y * inv + bb.y + rr.y)));
    o.z = 1.f / (1.f + expf(-(acc.z * inv + bb.z + rr.z)));
    o.w = 1.f / (1.f + expf(-(acc.w * inv + bb.w + rr.w)));
    *(float4*)(out + (size_t)node * 128 + c) = o;
}

// ---------------- launch ---------------------------------------------------------
extern "C" void kernel_launch(void* const* d_in, const int* in_sizes, int n_in,
                              void* d_out, int out_size) {
    (void)in_sizes; (void)n_in; (void)out_size;
    const float* x   = (const float*)d_in[0];
    const void*  ei  = d_in[1];
    const float* W1l = (const float*)d_in[2];
    const float* b1  = (const float*)d_in[3];
    const float* W1r = (const float*)d_in[4];
    const float* W2l = (const float*)d_in[5];
    const float* b2  = (const float*)d_in[6];
    const float* W2r = (const float*)d_in[7];
    float* out = (float*)d_out;

    cudaFuncSetAttribute(k_gemm_fused, cudaFuncAttributeMaxDynamicSharedMemorySize, SMEM_DYN);

    k_prep<<<(WPREP_N + NODES * 32 + 255) / 256, 256>>>(W1l, W1r, W2l, W2r, x);
    k_edges<<<(EDGES + 255) / 256, 256>>>(ei);
    k_alloc<<<(NODES + 255) / 256, 256>>>();
    k_fill<<<(EDGES + 255) / 256, 256>>>();
    k_gather1<<<(NODES * 32 + 255) / 256, 256>>>();
    k_gemm_fused<<<NTILES, 256, SMEM_DYN>>>(b1);
    k_gather2_final<<<(NODES * 32 + 255) / 256, 256>>>(b2, out);
}

// round 16
// speedup vs baseline: 1.0306x; 1.0306x over previous
#include <cuda_runtime.h>
#include <cuda_fp16.h>
#include <math.h>
#include <stdint.h>

#define NODES 50000
#define NODES_PAD 50048            // 391 tiles * 128
#define EDGES 800000
#define NTILES 391

// ---------------- scratch (static device globals; no allocs allowed) ----------
// Pure fp16 pipeline: activations and weights quantized to fp16, fp32 accum.
__device__ __align__(128) unsigned char g_a1[(size_t)NODES_PAD * 1024]; // [N][512 f16]: [0,512)B agg, [512,1024)B x
__device__ __align__(128) unsigned char g_a2[(size_t)NODES_PAD * 512];  // [N][256 f16]: h
__device__ __align__(128) unsigned char g_b1[256 * 1024];               // [256 n][512 f16]: W1l;W1r transposed
__device__ __align__(128) unsigned char g_b2[256 * 512];                // [256 n][256 f16]: W2l|W2r transposed
__device__ __align__(128) unsigned char g_pl[(size_t)NODES_PAD * 256];  // [N][128 f16]: h@W2l (gathered later)
__device__ __align__(128) float g_pr[(size_t)NODES_PAD * 128];          // [N][128 f32]: h@W2r (self term)
__device__ int            g_cnt [NODES];
__device__ float          g_inv [NODES];
__device__ uint32_t       g_sd  [EDGES];        // src | (dst << 16)
__device__ unsigned short g_rk  [EDGES];        // rank within dst bucket
__device__ int            g_off [NODES];
__device__ unsigned short g_esrc[EDGES];        // src ids grouped by dst (16-bit)
__device__ int            g_total;

// ---------------- PTX helpers ---------------------------------------------------
__device__ __forceinline__ uint32_t smem_u32(const void* p) {
    uint32_t a;
    asm("{ .reg .u64 t; cvta.to.shared.u64 t, %1; cvt.u32.u64 %0, t; }" : "=r"(a) : "l"(p));
    return a;
}
#define SW128(o) ((o) ^ (((o) >> 3) & 0x70))

__device__ __forceinline__ void cp16(uint32_t dst, const void* src) {
    asm volatile("cp.async.cg.shared.global [%0], [%1], 16;" :: "r"(dst), "l"(src));
}
#define CP_COMMIT() asm volatile("cp.async.commit_group;" ::: "memory")
#define CP_WAIT(n)  asm volatile("cp.async.wait_group %0;" :: "n"(n) : "memory")

__device__ __forceinline__ void ldsm4(uint32_t addr, uint32_t* r) {
    asm volatile("ldmatrix.sync.aligned.m8n8.x4.shared.b16 {%0,%1,%2,%3}, [%4];"
        : "=r"(r[0]), "=r"(r[1]), "=r"(r[2]), "=r"(r[3]) : "r"(addr));
}
__device__ __forceinline__ void mma16816(float* c, const uint32_t* a, uint32_t b0, uint32_t b1) {
    asm volatile("mma.sync.aligned.m16n8k16.row.col.f32.f16.f16.f32 "
        "{%0,%1,%2,%3}, {%4,%5,%6,%7}, {%8,%9}, {%0,%1,%2,%3};"
        : "+f"(c[0]), "+f"(c[1]), "+f"(c[2]), "+f"(c[3])
        : "r"(a[0]), "r"(a[1]), "r"(a[2]), "r"(a[3]), "r"(b0), "r"(b1));
}

__device__ __forceinline__ unsigned short f2h(float v) {
    __half h = __float2half_rn(v);
    return *reinterpret_cast<unsigned short*>(&h);
}
__device__ __forceinline__ uint32_t pack2h(float a, float b) {
    return (uint32_t)f2h(a) | ((uint32_t)f2h(b) << 16);
}
__device__ __forceinline__ float2 uph(uint32_t w) {
    return __half22float2(*reinterpret_cast<__half2*>(&w));
}

// ------- fused prep+edges: counters, weights->fp16, x->fp16, edge decode --------
// Disjoint work regions overlap across SMs inside a single launch.
#define WPREP_N (256 * 512 + 256 * 256)     // 196608
#define PREP_TOTAL (WPREP_N + NODES * 32)   // 1796608  (>= EDGES)
__global__ void k_prep_edges(const float* __restrict__ W1l, const float* __restrict__ W1r,
                             const float* __restrict__ W2l, const float* __restrict__ W2r,
                             const float* __restrict__ x,  const void* __restrict__ ei_raw) {
    int id = blockIdx.x * blockDim.x + threadIdx.x;
    if (id == 0) g_total = 0;
    // edge decode + degree count; atomic result IS the bucket rank
    if (id < EDGES) {
        const int* w = (const int*)ei_raw;
        bool is64 = ((w[1] | w[3] | w[5] | w[7] | w[9] | w[11] | w[13] | w[15]) == 0);
        int s, d;
        if (is64) {
            const long long* e64 = (const long long*)ei_raw;
            s = (int)e64[id];
            d = (int)e64[EDGES + id];
        } else {
            s = w[id];
            d = w[EDGES + id];
        }
        g_sd[id] = (uint32_t)s | ((uint32_t)d << 16);
        g_rk[id] = (unsigned short)atomicAdd(&g_cnt[d], 1);
    }
    // prep
    if (id < 256 * 512) {
        int n = id >> 9, k = id & 511;
        float w = (k < 256) ? W1l[k * 256 + n] : W1r[(k - 256) * 256 + n];
        *(unsigned short*)(g_b1 + (size_t)n * 1024 + 2 * k) = f2h(w);
    } else if (id < WPREP_N) {
        int id2 = id - 256 * 512;
        int n = id2 >> 8, k = id2 & 255;
        float w = (n < 128) ? W2l[k * 128 + n] : W2r[k * 128 + (n - 128)];
        *(unsigned short*)(g_b2 + (size_t)n * 512 + 2 * k) = f2h(w);
    } else if (id < PREP_TOTAL) {
        int id2 = id - WPREP_N;
        int node = id2 >> 5;
        int col  = (id2 & 31) * 8;
        const float4* src = (const float4*)(x + (size_t)node * 256 + col);
        float4 a = src[0], b = src[1];
        uint4 o;
        o.x = pack2h(a.x, a.y);
        o.y = pack2h(a.z, a.w);
        o.z = pack2h(b.x, b.y);
        o.w = pack2h(b.z, b.w);
        *(uint4*)(g_a1 + (size_t)node * 1024 + 512 + col * 2) = o;
    }
}

// zero counters must precede k_prep_edges' atomics
__global__ void k_zero() {
    int i = blockIdx.x * blockDim.x + threadIdx.x;
    if (i < NODES) g_cnt[i] = 0;
}

// ------- bucket allocation: per-block scan + one global atomic; also 1/deg -----
__global__ void k_alloc() {
    __shared__ int s[256];
    __shared__ int base;
    int t = threadIdx.x;
    int i = blockIdx.x * 256 + t;
    int v = (i < NODES) ? g_cnt[i] : 0;
    s[t] = v;
    __syncthreads();
#pragma unroll
    for (int d = 1; d < 256; d <<= 1) {
        int add = (t >= d) ? s[t - d] : 0;
        __syncthreads();
        s[t] += add;
        __syncthreads();
    }
    int incl = s[t];
    if (t == 255) base = atomicAdd(&g_total, incl);
    __syncthreads();
    if (i < NODES) {
        g_off[i] = base + incl - v;
        g_inv[i] = 1.f / fmaxf((float)v, 1.f);
    }
}

// ------- bucket fill: atomic-free scatter via precomputed rank ------------------
__global__ void k_fill() {
    int e = blockIdx.x * blockDim.x + threadIdx.x;
    if (e >= EDGES) return;
    uint32_t sd = g_sd[e];
    g_esrc[g_off[sd >> 16] + g_rk[e]] = (unsigned short)(sd & 0xFFFF);
}

// ------------- layer-1 gather (fp16 rows, fp32 accumulate) -----------------------
// One warp per node; lane owns 8 cols (16B fp16); 4-edge unroll.
__global__ void k_gather1() {
    int node = (blockIdx.x * blockDim.x + threadIdx.x) >> 5;
    if (node >= NODES) return;
    int lane = threadIdx.x & 31;
    int boff = lane * 16;

    int e   = g_off[node];
    int end = e + g_cnt[node];
    float acc[8];
#pragma unroll
    for (int i = 0; i < 8; i++) acc[i] = 0.f;

    for (; e + 3 < end; e += 4) {
        int s0 = g_esrc[e], s1 = g_esrc[e + 1], s2 = g_esrc[e + 2], s3 = g_esrc[e + 3];
        uint4 v0 = *(const uint4*)(g_a1 + (size_t)s0 * 1024 + 512 + boff);
        uint4 v1 = *(const uint4*)(g_a1 + (size_t)s1 * 1024 + 512 + boff);
        uint4 v2 = *(const uint4*)(g_a1 + (size_t)s2 * 1024 + 512 + boff);
        uint4 v3 = *(const uint4*)(g_a1 + (size_t)s3 * 1024 + 512 + boff);
        float2 f;
        f = uph(v0.x); acc[0] += f.x; acc[1] += f.y;
        f = uph(v0.y); acc[2] += f.x; acc[3] += f.y;
        f = uph(v0.z); acc[4] += f.x; acc[5] += f.y;
        f = uph(v0.w); acc[6] += f.x; acc[7] += f.y;
        f = uph(v1.x); acc[0] += f.x; acc[1] += f.y;
        f = uph(v1.y); acc[2] += f.x; acc[3] += f.y;
        f = uph(v1.z); acc[4] += f.x; acc[5] += f.y;
        f = uph(v1.w); acc[6] += f.x; acc[7] += f.y;
        f = uph(v2.x); acc[0] += f.x; acc[1] += f.y;
        f = uph(v2.y); acc[2] += f.x; acc[3] += f.y;
        f = uph(v2.z); acc[4] += f.x; acc[5] += f.y;
        f = uph(v2.w); acc[6] += f.x; acc[7] += f.y;
        f = uph(v3.x); acc[0] += f.x; acc[1] += f.y;
        f = uph(v3.y); acc[2] += f.x; acc[3] += f.y;
        f = uph(v3.z); acc[4] += f.x; acc[5] += f.y;
        f = uph(v3.w); acc[6] += f.x; acc[7] += f.y;
    }
    for (; e < end; e++) {
        int s0 = g_esrc[e];
        uint4 v0 = *(const uint4*)(g_a1 + (size_t)s0 * 1024 + 512 + boff);
        float2 f;
        f = uph(v0.x); acc[0] += f.x; acc[1] += f.y;
        f = uph(v0.y); acc[2] += f.x; acc[3] += f.y;
        f = uph(v0.z); acc[4] += f.x; acc[5] += f.y;
        f = uph(v0.w); acc[6] += f.x; acc[7] += f.y;
    }
    float inv = g_inv[node];
    uint4 o;
    o.x = pack2h(acc[0] * inv, acc[1] * inv);
    o.y = pack2h(acc[2] * inv, acc[3] * inv);
    o.z = pack2h(acc[4] * inv, acc[5] * inv);
    o.w = pack2h(acc[6] * inv, acc[7] * inv);
    *(uint4*)(g_a1 + (size_t)node * 1024 + boff) = o;
}

// ---------------- warp-MMA fp16 GEMM: D[128 rows, 128 cols] per CTA --------------
// MODE 1: A=g_a1 (K=512, 8 tiles), B=g_b1; epilogue bias+relu -> g_a2 fp16
// MODE 2: A=g_a2 (K=256, 4 tiles), B=g_b2; epilogue: left->g_pl fp16, right->g_pr f32
#define STAGE_BYTES 32768                 // A 16KB + B 16KB
#define SMEM_DYN (3 * STAGE_BYTES)

template <int MODE>
__global__ __launch_bounds__(256, 2) void k_gemm(const float* __restrict__ bias) {
    constexpr int RB = (MODE == 1) ? 1024 : 512;    // stream row bytes
    constexpr int KT = (MODE == 1) ? 8 : 4;         // 128-byte k-tiles (64 f16)
    const unsigned char* gA = (MODE == 1) ? g_a1 : g_a2;
    const unsigned char* gB = (MODE == 1) ? g_b1 : g_b2;

    extern __shared__ __align__(128) unsigned char dsm[];
    const int t      = threadIdx.x;
    const int lane   = t & 31;
    const int wid    = t >> 5;
    const int warp_m = wid & 3;
    const int warp_n = wid >> 2;
    const int row0   = blockIdx.y * 128;
    const int col0   = blockIdx.x * 128;
    const uint32_t base = smem_u32(dsm);

    float c[2][8][4];
#pragma unroll
    for (int i = 0; i < 2; i++)
#pragma unroll
        for (int j = 0; j < 8; j++)
#pragma unroll
            for (int q = 0; q < 4; q++) c[i][j][q] = 0.f;

    const int lrow = t >> 1;
    const int ch0  = (t & 1) * 4;

    auto load_tile = [&](int kt, int s) {
        uint32_t sa = base + s * STAGE_BYTES;
        uint32_t sb = sa + 16384;
        const unsigned char* srcA = gA + (size_t)(row0 + lrow) * RB + (size_t)kt * 128 + ch0 * 16;
#pragma unroll
        for (int i = 0; i < 4; i++)
            cp16(sa + SW128(lrow * 128 + (ch0 + i) * 16), srcA + i * 16);
        const unsigned char* srcB = gB + (size_t)(col0 + lrow) * RB + (size_t)kt * 128 + ch0 * 16;
#pragma unroll
        for (int i = 0; i < 4; i++)
            cp16(sb + SW128(lrow * 128 + (ch0 + i) * 16), srcB + i * 16);
        CP_COMMIT();
    };

    const int lj = lane >> 3;
    const int lr = lane & 7;

    auto compute = [&](int s) {
        uint32_t sa = base + s * STAGE_BYTES;
        uint32_t sb = sa + 16384;
#pragma unroll
        for (int ks = 0; ks < 4; ks++) {
            int cb = ks * 32 + (lj >> 1) * 16;
            uint32_t af[2][4];
#pragma unroll
            for (int mm = 0; mm < 2; mm++) {
                int row = warp_m * 32 + mm * 16 + (lj & 1) * 8 + lr;
                ldsm4(sa + SW128(row * 128 + cb), af[mm]);
            }
            uint32_t bf[4][4];
#pragma unroll
            for (int np = 0; np < 4; np++) {
                int row = warp_n * 64 + np * 16 + (lj & 1) * 8 + lr;
                ldsm4(sb + SW128(row * 128 + cb), bf[np]);
            }
#pragma unroll
            for (int mm = 0; mm < 2; mm++)
#pragma unroll
                for (int nn = 0; nn < 8; nn++)
                    mma16816(c[mm][nn], af[mm], bf[nn >> 1][nn & 1], bf[nn >> 1][(nn & 1) + 2]);
        }
    };

    load_tile(0, 0);
    load_tile(1, 1);
#pragma unroll 1
    for (int kt = 0; kt < KT; kt++) {
        if (kt == KT - 1) { CP_WAIT(0); } else { CP_WAIT(1); }
        __syncthreads();
        if (kt + 2 < KT) load_tile(kt + 2, (kt + 2) % 3);
        compute(kt % 3);
    }

    // ---------------- epilogue -------------------------------------------------
    const int qr = lane >> 2;
    const int qc = (lane & 3) * 2;
#pragma unroll
    for (int mm = 0; mm < 2; mm++) {
#pragma unroll
        for (int nn = 0; nn < 8; nn++) {
            int col = col0 + warp_n * 64 + nn * 8 + qc;
#pragma unroll
            for (int h = 0; h < 2; h++) {
                int row = row0 + warp_m * 32 + mm * 16 + qr + h * 8;
                float v0 = c[mm][nn][2 * h + 0];
                float v1 = c[mm][nn][2 * h + 1];
                if (MODE == 1) {
                    v0 = fmaxf(v0 + __ldg(&bias[col]), 0.f);
                    v1 = fmaxf(v1 + __ldg(&bias[col + 1]), 0.f);
                    *(uint32_t*)(g_a2 + (size_t)row * 512 + 2 * col) = pack2h(v0, v1);
                } else {
                    if (col < 128) {
                        *(uint32_t*)(g_pl + (size_t)row * 256 + 2 * col) = pack2h(v0, v1);
                    } else {
                        *(float2*)(g_pr + (size_t)row * 128 + (col - 128)) = make_float2(v0, v1);
                    }
                }
            }
        }
    }
}

// ---- layer-2 gather fused with epilogue: out = sigmoid(mean(p_l)+b2+p_r) -------
// One warp per node; lane owns 4 cols (8B fp16 per edge); 4-edge unroll.
__global__ void k_gather2_final(const float* __restrict__ b2,
                                float* __restrict__ out) {
    int node = (blockIdx.x * blockDim.x + threadIdx.x) >> 5;
    if (node >= NODES) return;
    int lane = threadIdx.x & 31;
    int c = lane * 4;

    int e   = g_off[node];
    int end = e + g_cnt[node];
    float4 acc = make_float4(0.f, 0.f, 0.f, 0.f);
    for (; e + 3 < end; e += 4) {
        int s0 = g_esrc[e], s1 = g_esrc[e + 1], s2 = g_esrc[e + 2], s3 = g_esrc[e + 3];
        uint2 v0 = *(const uint2*)(g_pl + (size_t)s0 * 256 + 2 * c);
        uint2 v1 = *(const uint2*)(g_pl + (size_t)s1 * 256 + 2 * c);
        uint2 v2 = *(const uint2*)(g_pl + (size_t)s2 * 256 + 2 * c);
        uint2 v3 = *(const uint2*)(g_pl + (size_t)s3 * 256 + 2 * c);
        float2 f;
        f = uph(v0.x); acc.x += f.x; acc.y += f.y;
        f = uph(v0.y); acc.z += f.x; acc.w += f.y;
        f = uph(v1.x); acc.x += f.x; acc.y += f.y;
        f = uph(v1.y); acc.z += f.x; acc.w += f.y;
        f = uph(v2.x); acc.x += f.x; acc.y += f.y;
        f = uph(v2.y); acc.z += f.x; acc.w += f.y;
        f = uph(v3.x); acc.x += f.x; acc.y += f.y;
        f = uph(v3.y); acc.z += f.x; acc.w += f.y;
    }
    for (; e < end; e++) {
        int s0 = g_esrc[e];
        uint2 v0 = *(const uint2*)(g_pl + (size_t)s0 * 256 + 2 * c);
        float2 f;
        f = uph(v0.x); acc.x += f.x; acc.y += f.y;
        f = uph(v0.y); acc.z += f.x; acc.w += f.y;
    }
    float inv = g_inv[node];
    float4 bb = *(const float4*)(b2 + c);
    float4 rr = *(const float4*)(g_pr + (size_t)node * 128 + c);
    float4 o;
    o.x = 1.f / (1.f + expf(-(acc.x * inv + bb.x + rr.x)));
    o.y = 1.f / (1.f + expf(-(acc.y * inv + bb.y + rr.y)));
    o.z = 1.f / (1.f + expf(-(acc.z * inv + bb.z + rr.z)));
    o.w = 1.f / (1.f + expf(-(acc.w * inv + bb.w + rr.w)));
    *(float4*)(out + (size_t)node * 128 + c) = o;
}

// ---------------- launch ---------------------------------------------------------
extern "C" void kernel_launch(void* const* d_in, const int* in_sizes, int n_in,
                              void* d_out, int out_size) {
    (void)in_sizes; (void)n_in; (void)out_size;
    const float* x   = (const float*)d_in[0];
    const void*  ei  = d_in[1];
    const float* W1l = (const float*)d_in[2];
    const float* b1  = (const float*)d_in[3];
    const float* W1r = (const float*)d_in[4];
    const float* W2l = (const float*)d_in[5];
    const float* b2  = (const float*)d_in[6];
    const float* W2r = (const float*)d_in[7];
    float* out = (float*)d_out;

    cudaFuncSetAttribute(k_gemm<1>, cudaFuncAttributeMaxDynamicSharedMemorySize, SMEM_DYN);
    cudaFuncSetAttribute(k_gemm<2>, cudaFuncAttributeMaxDynamicSharedMemorySize, SMEM_DYN);

    k_zero<<<(NODES + 255) / 256, 256>>>();
    k_prep_edges<<<(PREP_TOTAL + 255) / 256, 256>>>(W1l, W1r, W2l, W2r, x, ei);
    k_alloc<<<(NODES + 255) / 256, 256>>>();
    k_fill<<<(EDGES + 255) / 256, 256>>>();
    k_gather1<<<(NODES * 32 + 255) / 256, 256>>>();
    dim3 grid_g(2, NTILES);
    k_gemm<1><<<grid_g, 256, SMEM_DYN>>>(b1);
    k_gemm<2><<<grid_g, 256, SMEM_DYN>>>(b1 /*unused*/);
    k_gather2_final<<<(NODES * 32 + 255) / 256, 256>>>(b2, out);
}